// round 14
// baseline (speedup 1.0000x reference)
#include <cuda_runtime.h>
#include <cuda_fp16.h>
#include <math.h>
#include <stdint.h>

#define BATCH 64
#define NT    197
#define CH    768
#define NH    12
#define HD    64
#define BHN   (BATCH*NH)      // 768
#define ROWS  (BATCH*NT)      // 12608
#define QKN   (3*CH)          // 2304
#define KDIM  768
#define KC    64              // K per chunk
#define NCHUNK (KDIM/KC)      // 12

// 256x128 CTA tile, 512 threads, 16 warps (4x4 warp grid, warp tile 64x32)
#define TILEA  (256*KC*2)     // 32768 bytes (A: 256 rows x 128B)
#define TILEBB (128*KC*2)     // 16384 bytes (B: 128 rows x 128B)
#define STAGEB (2*TILEA + 2*TILEBB)   // 98304 per stage
#define DSMEM  (2*STAGEB + 128)       // ~192KB

#define WSCALE   64.0f
#define AOSCALE  64.0f
#define INV_QKV  (1.0f/64.0f)
#define INV_PROJ (1.0f/4096.0f)
#define QK_TAU   1.5e-3f

// ---------------- scratch ------------------------------------------------------
__device__ float               g_q[(size_t)BHN*NT*HD];
__device__ float               g_k[(size_t)BHN*NT*HD];
__device__ float               g_v[(size_t)BHN*NT*HD];
__device__ unsigned long long  g_qb[BHN*NT];
__device__ unsigned long long  g_kb[BHN*NT];
__device__ float               g_sq[BHN];
__device__ float               g_sk[BHN];
__device__ float               g_vinv[BHN*HD];
__device__ signed char         g_v8[(size_t)BHN*NT*HD];
__device__ float               g_bias[NH*NT*NT];
__device__ __align__(16) __half g_ah[(size_t)ROWS*CH];
__device__ __align__(16) __half g_al[(size_t)ROWS*CH];
__device__ __align__(16) __half g_wh[(size_t)QKN*CH];
__device__ __align__(16) __half g_wl[(size_t)QKN*CH];
__device__ __align__(16) __half g_ph[(size_t)CH*CH];
__device__ __align__(16) __half g_pl[(size_t)CH*CH];

// ---------------- PTX helpers -------------------------------------------------
__device__ __forceinline__ uint32_t s2u(const void* p) {
    uint32_t r;
    asm("{ .reg .u64 t; cvta.to.shared.u64 t, %1; cvt.u32.u64 %0, t; }" : "=r"(r) : "l"(p));
    return r;
}
__device__ __forceinline__ void cp16(uint32_t saddr, const void* gaddr, uint32_t srcsize) {
    asm volatile("cp.async.cg.shared.global [%0], [%1], 16, %2;"
                 :: "r"(saddr), "l"(gaddr), "r"(srcsize) : "memory");
}
__device__ __forceinline__ void cp_commit() {
    asm volatile("cp.async.commit_group;" ::: "memory");
}
template<int N> __device__ __forceinline__ void cp_wait() {
    asm volatile("cp.async.wait_group %0;" :: "n"(N) : "memory");
}
__device__ __forceinline__ void ldsm4(uint32_t a, uint32_t& r0, uint32_t& r1,
                                      uint32_t& r2, uint32_t& r3) {
    asm volatile("ldmatrix.sync.aligned.m8n8.x4.shared.b16 {%0,%1,%2,%3}, [%4];"
                 : "=r"(r0), "=r"(r1), "=r"(r2), "=r"(r3) : "r"(a));
}
__device__ __forceinline__ void mma16816(float* c, const uint32_t* a,
                                         uint32_t b0, uint32_t b1) {
    asm volatile("mma.sync.aligned.m16n8k16.row.col.f32.f16.f16.f32 "
                 "{%0,%1,%2,%3}, {%4,%5,%6,%7}, {%8,%9}, {%0,%1,%2,%3};"
                 : "+f"(c[0]), "+f"(c[1]), "+f"(c[2]), "+f"(c[3])
                 : "r"(a[0]), "r"(a[1]), "r"(a[2]), "r"(a[3]), "r"(b0), "r"(b1));
}
__device__ __forceinline__ int dp4a_us(unsigned int a, int b, int c) {
    int d;
    asm("dp4a.u32.s32 %0, %1, %2, %3;" : "=r"(d) : "r"(a), "r"(b), "r"(c));
    return d;
}

__device__ __forceinline__ float dot768(const float* __restrict__ xr,
                                        const float* __restrict__ wr)
{
    const float4* a4 = (const float4*)xr;
    const float4* b4 = (const float4*)wr;
    float s0 = 0.f, s1 = 0.f, s2 = 0.f, s3 = 0.f;
#pragma unroll 4
    for (int i = 0; i < CH / 4; i++) {
        float4 a = a4[i], b = b4[i];
        s0 = fmaf(a.x, b.x, s0);
        s1 = fmaf(a.y, b.y, s1);
        s2 = fmaf(a.z, b.z, s2);
        s3 = fmaf(a.w, b.w, s3);
    }
    return (s0 + s1) + (s2 + s3);
}

// ---------------- fp16 hi/lo split ---------------------------------------------
__device__ __forceinline__ void splith2(float x, float y, float s, uint32_t& h, uint32_t& l) {
    float xs = x * s, ys = y * s;
    __half hx = __float2half(xs), hy = __float2half(ys);
    __half lx = __float2half(xs - __half2float(hx));
    __half ly = __float2half(ys - __half2float(hy));
    h = (uint32_t)__half_as_ushort(hx) | ((uint32_t)__half_as_ushort(hy) << 16);
    l = (uint32_t)__half_as_ushort(lx) | ((uint32_t)__half_as_ushort(ly) << 16);
}
__global__ __launch_bounds__(256) void split8_k(const float* __restrict__ in,
                                                __half* __restrict__ hi,
                                                __half* __restrict__ lo,
                                                float s, int n8)
{
    int i = blockIdx.x * 256 + threadIdx.x;
    if (i >= n8) return;
    float4 a = ((const float4*)in)[i * 2];
    float4 b = ((const float4*)in)[i * 2 + 1];
    uint4 H, L;
    splith2(a.x, a.y, s, H.x, L.x);
    splith2(a.z, a.w, s, H.y, L.y);
    splith2(b.x, b.y, s, H.z, L.z);
    splith2(b.z, b.w, s, H.w, L.w);
    ((uint4*)hi)[i] = H;
    ((uint4*)lo)[i] = L;
}

// ---------------- mma.sync fp16x3 GEMM: 256x128 tile, 512 threads --------------
// Fused per-ks passes (R6/R13 accumulation order). 2-stage cp.async, KC=64.
// MODE 0: q/k outputs with |val|<QK_TAU are fp32-repaired INLINE in the
//         epilogue (identical dot768 -> identical values to the old repair_qk).
template<int MODE>
__global__ __launch_bounds__(512)
void gemm_mma(const __half* __restrict__ Ah, const __half* __restrict__ Al,
              const __half* __restrict__ Bh, const __half* __restrict__ Bl,
              const float* __restrict__ bias, float* __restrict__ Cout,
              const float* __restrict__ xf, const float* __restrict__ wf,
              int M, int Nn)
{
    extern __shared__ char dyn[];
    uint32_t dbase = s2u(dyn);
    uint32_t pad = (128u - (dbase & 127u)) & 127u;
    uint32_t S = dbase + pad;

    int t = threadIdx.x;
    int wid = t >> 5, l = t & 31;
    int m0 = blockIdx.y * 256;
    int n0 = blockIdx.x * 128;

    int lar = t >> 3, lac = t & 7;
    int lbr = t >> 2, lbc = (t & 3) << 1;

    int r8 = l & 7, mi = l >> 3;
    int rsel = ((mi & 1) << 3) + r8;
    int hm = mi >> 1;
    int wm = (wid >> 2) * 64;
    int wn = (wid & 3) * 32;

    uint32_t apart[4]; int ax[4];
#pragma unroll
    for (int i = 0; i < 4; i++) {
        int row = wm + i * 16 + rsel;
        apart[i] = (uint32_t)(row * 128);
        ax[i] = row & 7;
    }
    uint32_t bpart[2]; int bx[2];
#pragma unroll
    for (int jj = 0; jj < 2; jj++) {
        int row = wn + jj * 16 + rsel;
        bpart[jj] = (uint32_t)(row * 128);
        bx[jj] = row & 7;
    }

    float acc[4][4][4];
#pragma unroll
    for (int i = 0; i < 4; i++)
#pragma unroll
        for (int j = 0; j < 4; j++)
#pragma unroll
            for (int e = 0; e < 4; e++) acc[i][j][e] = 0.f;

    const __half* Asrc[2] = {Ah, Al};
    const __half* Bsrc[2] = {Bh, Bl};

    auto load_stage = [&](int c) {
        uint32_t st = S + (uint32_t)(c & 1) * STAGEB;
        int k0 = c * KC;
#pragma unroll
        for (int ti = 0; ti < 2; ti++) {
#pragma unroll
            for (int i = 0; i < 4; i++) {
                int rr = lar + i * 64;
                int grow = m0 + rr;
                uint32_t ss = st + (uint32_t)ti * TILEA + (uint32_t)(rr * 128)
                              + (uint32_t)((lac ^ (rr & 7)) << 4);
                const void* g = (const char*)Asrc[ti]
                              + (((size_t)grow * KDIM + k0 + lac * 8) * 2);
                cp16(ss, g, (grow < M) ? 16u : 0u);
            }
        }
#pragma unroll
        for (int ti = 0; ti < 2; ti++) {
#pragma unroll
            for (int i = 0; i < 2; i++) {
                int cc = lbc + i;
                uint32_t ss = st + 2u * TILEA + (uint32_t)ti * TILEBB
                              + (uint32_t)(lbr * 128)
                              + (uint32_t)((cc ^ (lbr & 7)) << 4);
                const void* g = (const char*)Bsrc[ti]
                              + (((size_t)(n0 + lbr) * KDIM + k0 + cc * 8) * 2);
                cp16(ss, g, 16u);
            }
        }
        cp_commit();
    };

    load_stage(0);

    for (int c = 0; c < NCHUNK; c++) {
        if (c + 1 < NCHUNK) { load_stage(c + 1); cp_wait<1>(); }
        else                { cp_wait<0>(); }
        __syncthreads();

        uint32_t st = S + (uint32_t)(c & 1) * STAGEB;
        uint32_t tAh = st;
        uint32_t tAl = st + TILEA;
        uint32_t tBh = st + 2 * TILEA;
        uint32_t tBl = st + 2 * TILEA + TILEBB;

#pragma unroll
        for (int ks = 0; ks < 4; ks++) {
            int cbase = ks * 2 + hm;
            uint32_t ah[4][4], al[4][4], bh[2][4], bl[2][4];
#pragma unroll
            for (int i = 0; i < 4; i++)
                ldsm4(tAh + apart[i] + (uint32_t)((cbase ^ ax[i]) << 4),
                      ah[i][0], ah[i][1], ah[i][2], ah[i][3]);
#pragma unroll
            for (int jj = 0; jj < 2; jj++)
                ldsm4(tBh + bpart[jj] + (uint32_t)((cbase ^ bx[jj]) << 4),
                      bh[jj][0], bh[jj][1], bh[jj][2], bh[jj][3]);
#pragma unroll
            for (int jj = 0; jj < 2; jj++)
                ldsm4(tBl + bpart[jj] + (uint32_t)((cbase ^ bx[jj]) << 4),
                      bl[jj][0], bl[jj][1], bl[jj][2], bl[jj][3]);
#pragma unroll
            for (int i = 0; i < 4; i++)
                ldsm4(tAl + apart[i] + (uint32_t)((cbase ^ ax[i]) << 4),
                      al[i][0], al[i][1], al[i][2], al[i][3]);

#pragma unroll
            for (int i = 0; i < 4; i++) {
                mma16816(acc[i][0], ah[i], bh[0][0], bh[0][2]);
                mma16816(acc[i][1], ah[i], bh[0][1], bh[0][3]);
                mma16816(acc[i][2], ah[i], bh[1][0], bh[1][2]);
                mma16816(acc[i][3], ah[i], bh[1][1], bh[1][3]);
            }
#pragma unroll
            for (int i = 0; i < 4; i++) {
                mma16816(acc[i][0], ah[i], bl[0][0], bl[0][2]);
                mma16816(acc[i][1], ah[i], bl[0][1], bl[0][3]);
                mma16816(acc[i][2], ah[i], bl[1][0], bl[1][2]);
                mma16816(acc[i][3], ah[i], bl[1][1], bl[1][3]);
            }
#pragma unroll
            for (int i = 0; i < 4; i++) {
                mma16816(acc[i][0], al[i], bh[0][0], bh[0][2]);
                mma16816(acc[i][1], al[i], bh[0][1], bh[0][3]);
                mma16816(acc[i][2], al[i], bh[1][0], bh[1][2]);
                mma16816(acc[i][3], al[i], bh[1][1], bh[1][3]);
            }
        }
        __syncthreads();
    }

    int gID = l >> 2, tig = l & 3;
    if (MODE == 0) {
        int which = n0 / CH;
        float* P = (which == 0) ? g_q : (which == 1) ? g_k : g_v;
        int rem0 = n0 - which * CH;
        bool is_qk = (which < 2);
#pragma unroll
        for (int i = 0; i < 4; i++) {
#pragma unroll
            for (int half = 0; half < 2; half++) {
                int m = m0 + wm + i * 16 + gID + half * 8;
                if (m >= M) continue;
                int b = m / NT, n = m - b * NT;
                const float* xr = xf + (size_t)m * CH;
#pragma unroll
                for (int j = 0; j < 4; j++) {
                    int rem = rem0 + wn + j * 8 + tig * 2;
                    int h = rem >> 6, d = rem & 63;
                    float v0 = (half ? acc[i][j][2] : acc[i][j][0]) * INV_QKV;
                    float v1 = (half ? acc[i][j][3] : acc[i][j][1]) * INV_QKV;
                    if (is_qk) {
                        if (fabsf(v0) < QK_TAU)
                            v0 = dot768(xr, wf + (size_t)(which * CH + rem) * CH);
                        if (fabsf(v1) < QK_TAU)
                            v1 = dot768(xr, wf + (size_t)(which * CH + rem + 1) * CH);
                    }
                    *(float2*)&P[(((size_t)(b * NH + h)) * NT + n) * HD + d]
                        = make_float2(v0, v1);
                }
            }
        }
    } else {
#pragma unroll
        for (int i = 0; i < 4; i++) {
#pragma unroll
            for (int half = 0; half < 2; half++) {
                int m = m0 + wm + i * 16 + gID + half * 8;
                if (m >= M) continue;
                float* crow = Cout + (size_t)m * CH;
#pragma unroll
                for (int j = 0; j < 4; j++) {
                    int cg = n0 + wn + j * 8 + tig * 2;
                    float2 bb2 = *(const float2*)&bias[cg];
                    float2 v2 = half
                        ? make_float2(acc[i][j][2] * INV_PROJ + bb2.x, acc[i][j][3] * INV_PROJ + bb2.y)
                        : make_float2(acc[i][j][0] * INV_PROJ + bb2.x, acc[i][j][1] * INV_PROJ + bb2.y);
                    *(float2*)&crow[cg] = v2;
                }
            }
        }
    }
}

// -------- per-(b,h) stats + v int8 quant with fp32 boundary repair ------------
__global__ __launch_bounds__(256) void stats_k(const float* __restrict__ x,
                                               const float* __restrict__ wqkv)
{
    int bh = blockIdx.x;
    size_t base = (size_t)bh * NT * HD;
    const float* q = g_q + base;
    const float* k = g_k + base;
    const float* v = g_v + base;
    int tid = threadIdx.x, w = tid >> 5, l = tid & 31;
    int b = bh / NH, hh = bh - b * NH;

    __shared__ int   vmax[HD];
    __shared__ float svs[HD];
    __shared__ float r1[8], r2[8];
    if (tid < HD) vmax[tid] = 0;
    __syncthreads();

    float sa = 0.f, sb = 0.f;
    for (int i = tid; i < NT * HD; i += 256) {
        sa += fabsf(q[i]);
        sb += fabsf(k[i]);
        atomicMax(&vmax[i & 63], __float_as_int(fabsf(v[i])));
    }
#pragma unroll
    for (int o = 16; o; o >>= 1) {
        sa += __shfl_xor_sync(0xffffffffu, sa, o);
        sb += __shfl_xor_sync(0xffffffffu, sb, o);
    }
    if (l == 0) { r1[w] = sa; r2[w] = sb; }

    for (int n = w; n < NT; n += 8) {
        float q0 = q[n * HD + l],      q1 = q[n * HD + 32 + l];
        float k0 = k[n * HD + l],      k1 = k[n * HD + 32 + l];
        unsigned bq0 = __ballot_sync(0xffffffffu, q0 < 0.f);
        unsigned bq1 = __ballot_sync(0xffffffffu, q1 < 0.f);
        unsigned bk0 = __ballot_sync(0xffffffffu, k0 < 0.f);
        unsigned bk1 = __ballot_sync(0xffffffffu, k1 < 0.f);
        if (l == 0) {
            g_qb[bh * NT + n] = (unsigned long long)bq0 | ((unsigned long long)bq1 << 32);
            g_kb[bh * NT + n] = (unsigned long long)bk0 | ((unsigned long long)bk1 << 32);
        }
    }
    __syncthreads();

    if (tid == 0) {
        float s1 = 0.f, s2 = 0.f;
        for (int i = 0; i < 8; i++) { s1 += r1[i]; s2 += r2[i]; }
        g_sq[bh] = s1 / (float)(NT * HD);
        g_sk[bh] = s2 / (float)(NT * HD);
    }
    if (tid < HD) {
        float mm = __int_as_float(vmax[tid]);
        float s = 127.f / (mm + 1e-6f);
        svs[tid] = s;
        g_vinv[bh * HD + tid] = 1.f / (s + 1e-6f);
    }
    __syncthreads();
    for (int i = tid; i < NT * HD; i += 256) {
        float vv = v[i];
        int d = i & 63;
        float tq = vv * svs[d];
        if (fabsf(tq - rintf(tq)) > 0.498f) {
            int n = i >> 6;
            const float* xr = x + (size_t)(b * NT + n) * CH;
            const float* wr = wqkv + (size_t)(2 * CH + hh * HD + d) * CH;
            vv = dot768(xr, wr);
            tq = vv * svs[d];
        }
        g_v8[base + i] = (signed char)rintf(tq);
    }
}

// -------- relative-position bias gather ---------------------------------------
__global__ __launch_bounds__(256) void bias_k(const float* __restrict__ rpb,
                                              const int* __restrict__ rel)
{
    int i = blockIdx.x * 256 + threadIdx.x;
    if (i < NH * NT * NT) {
        int h = i / (NT * NT);
        int r = i - h * (NT * NT);
        g_bias[i] = rpb[rel[r] * NH + h];
    }
}

// -------- fused attention v2: 4-row batched AV, int4 smem loads ----------------
#define VROW 208
__global__ __launch_bounds__(256) void attn_k()
{
    __shared__ unsigned long long skb[NT];
    __shared__ __align__(16) signed char  svt[HD * VROW];
    __shared__ __align__(16) unsigned char pbuf[32 * VROW];

    int bh = blockIdx.x;
    int half = blockIdx.y;
    int b = bh / NH, h = bh - b * NH;
    size_t base = (size_t)bh * NT * HD;
    int tid = threadIdx.x, w = tid >> 5, l = tid & 31;

    for (int i = tid; i < 32 * VROW / 4; i += 256) ((uint32_t*)pbuf)[i] = 0u;
    for (int i = tid; i < NT * HD; i += 256) {
        int n = i >> 6, d = i & 63;
        svt[d * VROW + n] = g_v8[base + i];
    }
    for (int i = tid; i < NT; i += 256) skb[i] = g_kb[bh * NT + i];
    __syncthreads();

    float p0 = g_sq[bh] * g_sk[bh];
    float fin0 = g_vinv[bh * HD + l]      * (1.0f / 255.0f) * AOSCALE;
    float fin1 = g_vinv[bh * HD + 32 + l] * (1.0f / 255.0f) * AOSCALE;
    const float* brow_base = g_bias + (size_t)h * NT * NT;
    const int4* sv0q = (const int4*)(svt + (size_t)l * VROW);
    const int4* sv1q = (const int4*)(svt + (size_t)(l + 32) * VROW);

    int nbase = 8 * half + w;
    int T = (NT - nbase + 15) / 16;
    int ngroups = T >> 2, tail = T & 3;

    auto softmax_row = [&](int n, int pr) {
        unsigned long long qb = g_qb[bh * NT + n];
        const float* brow = brow_base + (size_t)n * NT;
        float lg[7];
        float mx = -3.0e38f;
#pragma unroll
        for (int j = 0; j < 7; j++) {
            int m = j * 32 + l;
            float val = -3.0e38f;
            if (m < NT) {
                int cnt = 64 - 2 * __popcll(qb ^ skb[m]);
                val = 0.125f * (p0 * (float)cnt) + brow[m];
            }
            lg[j] = val;
            mx = fmaxf(mx, val);
        }
#pragma unroll
        for (int o = 16; o; o >>= 1) mx = fmaxf(mx, __shfl_xor_sync(0xffffffffu, mx, o));
        float sum = 0.f;
#pragma unroll
        for (int j = 0; j < 7; j++) {
            float e = expf(lg[j] - mx);
            lg[j] = e;
            sum += e;
        }
#pragma unroll
        for (int o = 16; o; o >>= 1) sum += __shfl_xor_sync(0xffffffffu, sum, o);
        float rs = 255.f / sum;
        unsigned char* pw = pbuf + pr * VROW;
#pragma unroll
        for (int j = 0; j < 7; j++) {
            int m = j * 32 + l;
            if (m < NT)
                pw[m] = (unsigned char)(int)fminf(rintf(lg[j] * rs), 255.f);
        }
    };

    auto store_row = [&](int n, int ia0, int ia1) {
        float o0 = (float)ia0 * fin0;
        float o1 = (float)ia1 * fin1;
        size_t ob = ((size_t)(b * NT + n)) * CH + h * HD;
        __half h0 = __float2half(o0);
        __half h1 = __float2half(o1);
        g_ah[ob + l]      = h0;
        g_al[ob + l]      = __float2half(o0 - __half2float(h0));
        g_ah[ob + 32 + l] = h1;
        g_al[ob + 32 + l] = __float2half(o1 - __half2float(h1));
    };

    for (int s = 0; s < ngroups; s++) {
        int n0r = nbase + 64 * s;
        __syncwarp();
#pragma unroll
        for (int r = 0; r < 4; r++) softmax_row(n0r + 16 * r, w * 4 + r);
        __syncwarp();

        const int4* pq0 = (const int4*)(pbuf + (w * 4 + 0) * VROW);
        const int4* pq1 = (const int4*)(pbuf + (w * 4 + 1) * VROW);
        const int4* pq2 = (const int4*)(pbuf + (w * 4 + 2) * VROW);
        const int4* pq3 = (const int4*)(pbuf + (w * 4 + 3) * VROW);
        int ia[4][2];
#pragma unroll
        for (int r = 0; r < 4; r++) { ia[r][0] = 0; ia[r][1] = 0; }

#pragma unroll
        for (int gq = 0; gq < VROW / 16; gq++) {
            int4 v0 = sv0q[gq];
            int4 v1 = sv1q[gq];
            int4 pr[4] = {pq0[gq], pq1[gq], pq2[gq], pq3[gq]};
#pragma unroll
            for (int r = 0; r < 4; r++) {
                ia[r][0] = dp4a_us((unsigned)pr[r].x, v0.x, ia[r][0]);
                ia[r][0] = dp4a_us((unsigned)pr[r].y, v0.y, ia[r][0]);
                ia[r][0] = dp4a_us((unsigned)pr[r].z, v0.z, ia[r][0]);
                ia[r][0] = dp4a_us((unsigned)pr[r].w, v0.w, ia[r][0]);
                ia[r][1] = dp4a_us((unsigned)pr[r].x, v1.x, ia[r][1]);
                ia[r][1] = dp4a_us((unsigned)pr[r].y, v1.y, ia[r][1]);
                ia[r][1] = dp4a_us((unsigned)pr[r].z, v1.z, ia[r][1]);
                ia[r][1] = dp4a_us((unsigned)pr[r].w, v1.w, ia[r][1]);
            }
        }
#pragma unroll
        for (int r = 0; r < 4; r++) store_row(n0r + 16 * r, ia[r][0], ia[r][1]);
    }

    if (tail) {
        int n = nbase + 64 * ngroups;
        __syncwarp();
        softmax_row(n, w * 4);
        __syncwarp();
        const int4* pq = (const int4*)(pbuf + (w * 4) * VROW);
        int ia0 = 0, ia1 = 0;
#pragma unroll
        for (int gq = 0; gq < VROW / 16; gq++) {
            int4 v0 = sv0q[gq];
            int4 v1 = sv1q[gq];
            int4 p = pq[gq];
            ia0 = dp4a_us((unsigned)p.x, v0.x, ia0);
            ia0 = dp4a_us((unsigned)p.y, v0.y, ia0);
            ia0 = dp4a_us((unsigned)p.z, v0.z, ia0);
            ia0 = dp4a_us((unsigned)p.w, v0.w, ia0);
            ia1 = dp4a_us((unsigned)p.x, v1.x, ia1);
            ia1 = dp4a_us((unsigned)p.y, v1.y, ia1);
            ia1 = dp4a_us((unsigned)p.z, v1.z, ia1);
            ia1 = dp4a_us((unsigned)p.w, v1.w, ia1);
        }
        store_row(n, ia0, ia1);
    }
}

// ---------------- launch ------------------------------------------------------
extern "C" void kernel_launch(void* const* d_in, const int* in_sizes, int n_in,
                              void* d_out, int out_size)
{
    const float* x     = (const float*)d_in[0];
    const float* wqkv  = (const float*)d_in[1];
    const float* wproj = (const float*)d_in[2];
    const float* bproj = (const float*)d_in[3];
    const float* rpb   = (const float*)d_in[4];
    const int*   rel   = (const int*)d_in[5];
    float* out = (float*)d_out;

    void *p_ah, *p_al, *p_wh, *p_wl, *p_ph, *p_pl;
    cudaGetSymbolAddress(&p_ah, g_ah);
    cudaGetSymbolAddress(&p_al, g_al);
    cudaGetSymbolAddress(&p_wh, g_wh);
    cudaGetSymbolAddress(&p_wl, g_wl);
    cudaGetSymbolAddress(&p_ph, g_ph);
    cudaGetSymbolAddress(&p_pl, g_pl);

    cudaFuncSetAttribute(gemm_mma<0>, cudaFuncAttributeMaxDynamicSharedMemorySize, DSMEM);
    cudaFuncSetAttribute(gemm_mma<1>, cudaFuncAttributeMaxDynamicSharedMemorySize, DSMEM);

    int n8x = ROWS * CH / 8;
    int n8w = QKN * CH / 8;
    int n8p = CH * CH / 8;
    split8_k<<<(n8x + 255) / 256, 256>>>(x, (__half*)p_ah, (__half*)p_al, 1.0f, n8x);
    split8_k<<<(n8w + 255) / 256, 256>>>(wqkv, (__half*)p_wh, (__half*)p_wl, WSCALE, n8w);
    split8_k<<<(n8p + 255) / 256, 256>>>(wproj, (__half*)p_ph, (__half*)p_pl, WSCALE, n8p);

    gemm_mma<0><<<dim3(QKN / 128, (ROWS + 255) / 256), 512, DSMEM>>>(
        (const __half*)p_ah, (const __half*)p_al,
        (const __half*)p_wh, (const __half*)p_wl,
        nullptr, nullptr, x, wqkv, ROWS, QKN);

    stats_k<<<BHN, 256>>>(x, wqkv);
    bias_k<<<(NH * NT * NT + 255) / 256, 256>>>(rpb, rel);

    attn_k<<<dim3(BHN, 2), 256>>>();

    gemm_mma<1><<<dim3(CH / 128, (ROWS + 255) / 256), 512, DSMEM>>>(
        (const __half*)p_ah, (const __half*)p_al,
        (const __half*)p_ph, (const __half*)p_pl,
        bproj, out, nullptr, nullptr, ROWS, CH);
}

// round 15
// speedup vs baseline: 1.3736x; 1.3736x over previous
#include <cuda_runtime.h>
#include <cuda_fp16.h>
#include <math.h>
#include <stdint.h>

#define BATCH 64
#define NT    197
#define CH    768
#define NH    12
#define HD    64
#define BHN   (BATCH*NH)      // 768
#define ROWS  (BATCH*NT)      // 12608
#define QKN   (3*CH)          // 2304
#define KDIM  768
#define KC    64              // K per chunk
#define NCHUNK (KDIM/KC)      // 12

// 256x128 CTA tile, 512 threads, 16 warps (4x4 warp grid, warp tile 64x32)
#define TILEA  (256*KC*2)     // 32768 bytes (A: 256 rows x 128B)
#define TILEBB (128*KC*2)     // 16384 bytes (B: 128 rows x 128B)
#define STAGEB (2*TILEA + 2*TILEBB)   // 98304 per stage
#define DSMEM  (2*STAGEB + 128)       // ~192KB

#define WSCALE   64.0f
#define AOSCALE  64.0f
#define INV_QKV  (1.0f/64.0f)
#define INV_PROJ (1.0f/4096.0f)
#define QK_TAU   1.5e-3f
#define WLCAP    (1 << 20)    // worklist capacity (expected ~46K entries)

// ---------------- scratch ------------------------------------------------------
__device__ float               g_q[(size_t)BHN*NT*HD];
__device__ float               g_k[(size_t)BHN*NT*HD];
__device__ float               g_v[(size_t)BHN*NT*HD];
__device__ unsigned long long  g_qb[BHN*NT];
__device__ unsigned long long  g_kb[BHN*NT];
__device__ float               g_sq[BHN];
__device__ float               g_sk[BHN];
__device__ float               g_vinv[BHN*HD];
__device__ signed char         g_v8[(size_t)BHN*NT*HD];
__device__ float               g_bias[NH*NT*NT];
__device__ unsigned int        g_wl[WLCAP];
__device__ int                 g_wcnt;
__device__ __align__(16) __half g_ah[(size_t)ROWS*CH];
__device__ __align__(16) __half g_al[(size_t)ROWS*CH];
__device__ __align__(16) __half g_wh[(size_t)QKN*CH];
__device__ __align__(16) __half g_wl16[(size_t)QKN*CH];
__device__ __align__(16) __half g_ph[(size_t)CH*CH];
__device__ __align__(16) __half g_pl[(size_t)CH*CH];

// ---------------- PTX helpers -------------------------------------------------
__device__ __forceinline__ uint32_t s2u(const void* p) {
    uint32_t r;
    asm("{ .reg .u64 t; cvta.to.shared.u64 t, %1; cvt.u32.u64 %0, t; }" : "=r"(r) : "l"(p));
    return r;
}
__device__ __forceinline__ void cp16(uint32_t saddr, const void* gaddr, uint32_t srcsize) {
    asm volatile("cp.async.cg.shared.global [%0], [%1], 16, %2;"
                 :: "r"(saddr), "l"(gaddr), "r"(srcsize) : "memory");
}
__device__ __forceinline__ void cp_commit() {
    asm volatile("cp.async.commit_group;" ::: "memory");
}
template<int N> __device__ __forceinline__ void cp_wait() {
    asm volatile("cp.async.wait_group %0;" :: "n"(N) : "memory");
}
__device__ __forceinline__ void ldsm4(uint32_t a, uint32_t& r0, uint32_t& r1,
                                      uint32_t& r2, uint32_t& r3) {
    asm volatile("ldmatrix.sync.aligned.m8n8.x4.shared.b16 {%0,%1,%2,%3}, [%4];"
                 : "=r"(r0), "=r"(r1), "=r"(r2), "=r"(r3) : "r"(a));
}
__device__ __forceinline__ void mma16816(float* c, const uint32_t* a,
                                         uint32_t b0, uint32_t b1) {
    asm volatile("mma.sync.aligned.m16n8k16.row.col.f32.f16.f16.f32 "
                 "{%0,%1,%2,%3}, {%4,%5,%6,%7}, {%8,%9}, {%0,%1,%2,%3};"
                 : "+f"(c[0]), "+f"(c[1]), "+f"(c[2]), "+f"(c[3])
                 : "r"(a[0]), "r"(a[1]), "r"(a[2]), "r"(a[3]), "r"(b0), "r"(b1));
}
__device__ __forceinline__ int dp4a_us(unsigned int a, int b, int c) {
    int d;
    asm("dp4a.u32.s32 %0, %1, %2, %3;" : "=r"(d) : "r"(a), "r"(b), "r"(c));
    return d;
}

__device__ __forceinline__ float dot768(const float* __restrict__ xr,
                                        const float* __restrict__ wr)
{
    const float4* a4 = (const float4*)xr;
    const float4* b4 = (const float4*)wr;
    float s0 = 0.f, s1 = 0.f, s2 = 0.f, s3 = 0.f;
#pragma unroll 4
    for (int i = 0; i < CH / 4; i++) {
        float4 a = a4[i], b = b4[i];
        s0 = fmaf(a.x, b.x, s0);
        s1 = fmaf(a.y, b.y, s1);
        s2 = fmaf(a.z, b.z, s2);
        s3 = fmaf(a.w, b.w, s3);
    }
    return (s0 + s1) + (s2 + s3);
}

// ---------------- fp16 hi/lo split ---------------------------------------------
__device__ __forceinline__ void splith2(float x, float y, float s, uint32_t& h, uint32_t& l) {
    float xs = x * s, ys = y * s;
    __half hx = __float2half(xs), hy = __float2half(ys);
    __half lx = __float2half(xs - __half2float(hx));
    __half ly = __float2half(ys - __half2float(hy));
    h = (uint32_t)__half_as_ushort(hx) | ((uint32_t)__half_as_ushort(hy) << 16);
    l = (uint32_t)__half_as_ushort(lx) | ((uint32_t)__half_as_ushort(ly) << 16);
}
__global__ __launch_bounds__(256) void split8_k(const float* __restrict__ in,
                                                __half* __restrict__ hi,
                                                __half* __restrict__ lo,
                                                float s, int n8)
{
    int i = blockIdx.x * 256 + threadIdx.x;
    if (i >= n8) return;
    float4 a = ((const float4*)in)[i * 2];
    float4 b = ((const float4*)in)[i * 2 + 1];
    uint4 H, L;
    splith2(a.x, a.y, s, H.x, L.x);
    splith2(a.z, a.w, s, H.y, L.y);
    splith2(b.x, b.y, s, H.z, L.z);
    splith2(b.z, b.w, s, H.w, L.w);
    ((uint4*)hi)[i] = H;
    ((uint4*)lo)[i] = L;
}

__global__ void reset_k() { g_wcnt = 0; }

// ---------------- mma.sync fp16x3 GEMM (R13 verbatim) --------------------------
template<int MODE>
__global__ __launch_bounds__(512)
void gemm_mma(const __half* __restrict__ Ah, const __half* __restrict__ Al,
              const __half* __restrict__ Bh, const __half* __restrict__ Bl,
              const float* __restrict__ bias, float* __restrict__ Cout, int M, int Nn)
{
    extern __shared__ char dyn[];
    uint32_t dbase = s2u(dyn);
    uint32_t pad = (128u - (dbase & 127u)) & 127u;
    uint32_t S = dbase + pad;

    int t = threadIdx.x;
    int wid = t >> 5, l = t & 31;
    int m0 = blockIdx.y * 256;
    int n0 = blockIdx.x * 128;

    int lar = t >> 3, lac = t & 7;
    int lbr = t >> 2, lbc = (t & 3) << 1;

    int r8 = l & 7, mi = l >> 3;
    int rsel = ((mi & 1) << 3) + r8;
    int hm = mi >> 1;
    int wm = (wid >> 2) * 64;
    int wn = (wid & 3) * 32;

    uint32_t apart[4]; int ax[4];
#pragma unroll
    for (int i = 0; i < 4; i++) {
        int row = wm + i * 16 + rsel;
        apart[i] = (uint32_t)(row * 128);
        ax[i] = row & 7;
    }
    uint32_t bpart[2]; int bx[2];
#pragma unroll
    for (int jj = 0; jj < 2; jj++) {
        int row = wn + jj * 16 + rsel;
        bpart[jj] = (uint32_t)(row * 128);
        bx[jj] = row & 7;
    }

    float acc[4][4][4];
#pragma unroll
    for (int i = 0; i < 4; i++)
#pragma unroll
        for (int j = 0; j < 4; j++)
#pragma unroll
            for (int e = 0; e < 4; e++) acc[i][j][e] = 0.f;

    const __half* Asrc[2] = {Ah, Al};
    const __half* Bsrc[2] = {Bh, Bl};

    auto load_stage = [&](int c) {
        uint32_t st = S + (uint32_t)(c & 1) * STAGEB;
        int k0 = c * KC;
#pragma unroll
        for (int ti = 0; ti < 2; ti++) {
#pragma unroll
            for (int i = 0; i < 4; i++) {
                int rr = lar + i * 64;
                int grow = m0 + rr;
                uint32_t ss = st + (uint32_t)ti * TILEA + (uint32_t)(rr * 128)
                              + (uint32_t)((lac ^ (rr & 7)) << 4);
                const void* g = (const char*)Asrc[ti]
                              + (((size_t)grow * KDIM + k0 + lac * 8) * 2);
                cp16(ss, g, (grow < M) ? 16u : 0u);
            }
        }
#pragma unroll
        for (int ti = 0; ti < 2; ti++) {
#pragma unroll
            for (int i = 0; i < 2; i++) {
                int cc = lbc + i;
                uint32_t ss = st + 2u * TILEA + (uint32_t)ti * TILEBB
                              + (uint32_t)(lbr * 128)
                              + (uint32_t)((cc ^ (lbr & 7)) << 4);
                const void* g = (const char*)Bsrc[ti]
                              + (((size_t)(n0 + lbr) * KDIM + k0 + cc * 8) * 2);
                cp16(ss, g, 16u);
            }
        }
        cp_commit();
    };

    load_stage(0);

    for (int c = 0; c < NCHUNK; c++) {
        if (c + 1 < NCHUNK) { load_stage(c + 1); cp_wait<1>(); }
        else                { cp_wait<0>(); }
        __syncthreads();

        uint32_t st = S + (uint32_t)(c & 1) * STAGEB;
        uint32_t tAh = st;
        uint32_t tAl = st + TILEA;
        uint32_t tBh = st + 2 * TILEA;
        uint32_t tBl = st + 2 * TILEA + TILEBB;

#pragma unroll
        for (int ks = 0; ks < 4; ks++) {
            int cbase = ks * 2 + hm;
            uint32_t ah[4][4], al[4][4], bh[2][4], bl[2][4];
#pragma unroll
            for (int i = 0; i < 4; i++)
                ldsm4(tAh + apart[i] + (uint32_t)((cbase ^ ax[i]) << 4),
                      ah[i][0], ah[i][1], ah[i][2], ah[i][3]);
#pragma unroll
            for (int jj = 0; jj < 2; jj++)
                ldsm4(tBh + bpart[jj] + (uint32_t)((cbase ^ bx[jj]) << 4),
                      bh[jj][0], bh[jj][1], bh[jj][2], bh[jj][3]);
#pragma unroll
            for (int jj = 0; jj < 2; jj++)
                ldsm4(tBl + bpart[jj] + (uint32_t)((cbase ^ bx[jj]) << 4),
                      bl[jj][0], bl[jj][1], bl[jj][2], bl[jj][3]);
#pragma unroll
            for (int i = 0; i < 4; i++)
                ldsm4(tAl + apart[i] + (uint32_t)((cbase ^ ax[i]) << 4),
                      al[i][0], al[i][1], al[i][2], al[i][3]);

#pragma unroll
            for (int i = 0; i < 4; i++) {
                mma16816(acc[i][0], ah[i], bh[0][0], bh[0][2]);
                mma16816(acc[i][1], ah[i], bh[0][1], bh[0][3]);
                mma16816(acc[i][2], ah[i], bh[1][0], bh[1][2]);
                mma16816(acc[i][3], ah[i], bh[1][1], bh[1][3]);
            }
#pragma unroll
            for (int i = 0; i < 4; i++) {
                mma16816(acc[i][0], ah[i], bl[0][0], bl[0][2]);
                mma16816(acc[i][1], ah[i], bl[0][1], bl[0][3]);
                mma16816(acc[i][2], ah[i], bl[1][0], bl[1][2]);
                mma16816(acc[i][3], ah[i], bl[1][1], bl[1][3]);
            }
#pragma unroll
            for (int i = 0; i < 4; i++) {
                mma16816(acc[i][0], al[i], bh[0][0], bh[0][2]);
                mma16816(acc[i][1], al[i], bh[0][1], bh[0][3]);
                mma16816(acc[i][2], al[i], bh[1][0], bh[1][2]);
                mma16816(acc[i][3], al[i], bh[1][1], bh[1][3]);
            }
        }
        __syncthreads();
    }

    int gID = l >> 2, tig = l & 3;
    if (MODE == 0) {
        int which = n0 / CH;
        float* P = (which == 0) ? g_q : (which == 1) ? g_k : g_v;
        int rem0 = n0 - which * CH;
#pragma unroll
        for (int i = 0; i < 4; i++) {
#pragma unroll
            for (int half = 0; half < 2; half++) {
                int m = m0 + wm + i * 16 + gID + half * 8;
                if (m >= M) continue;
                int b = m / NT, n = m - b * NT;
#pragma unroll
                for (int j = 0; j < 4; j++) {
                    int rem = rem0 + wn + j * 8 + tig * 2;
                    int h = rem >> 6, d = rem & 63;
                    float2 v2 = half
                        ? make_float2(acc[i][j][2] * INV_QKV, acc[i][j][3] * INV_QKV)
                        : make_float2(acc[i][j][0] * INV_QKV, acc[i][j][1] * INV_QKV);
                    *(float2*)&P[(((size_t)(b * NH + h)) * NT + n) * HD + d] = v2;
                }
            }
        }
    } else {
#pragma unroll
        for (int i = 0; i < 4; i++) {
#pragma unroll
            for (int half = 0; half < 2; half++) {
                int m = m0 + wm + i * 16 + gID + half * 8;
                if (m >= M) continue;
                float* crow = Cout + (size_t)m * CH;
#pragma unroll
                for (int j = 0; j < 4; j++) {
                    int cg = n0 + wn + j * 8 + tig * 2;
                    float2 bb2 = *(const float2*)&bias[cg];
                    float2 v2 = half
                        ? make_float2(acc[i][j][2] * INV_PROJ + bb2.x, acc[i][j][3] * INV_PROJ + bb2.y)
                        : make_float2(acc[i][j][0] * INV_PROJ + bb2.x, acc[i][j][1] * INV_PROJ + bb2.y);
                    *(float2*)&crow[cg] = v2;
                }
            }
        }
    }
}

// -------- scan: vectorized pass over q/k, append near-zero indices -------------
__global__ __launch_bounds__(256) void scan_k()
{
    const int PER = BHN * NT * HD;
    int idx4 = blockIdx.x * 256 + threadIdx.x;
    int tot4 = 2 * PER / 4;
    if (idx4 >= tot4) return;
    int t = idx4 >= (PER / 4);
    int r4 = idx4 - t * (PER / 4);
    const float4 v = ((const float4*)(t ? g_k : g_q))[r4];
    float a[4] = {v.x, v.y, v.z, v.w};
#pragma unroll
    for (int j = 0; j < 4; j++) {
        if (fabsf(a[j]) < QK_TAU) {
            int pos = atomicAdd(&g_wcnt, 1);
            if (pos < WLCAP)
                g_wl[pos] = (unsigned)(r4 * 4 + j) | ((unsigned)t << 31);
        }
    }
}

// -------- fix: one warp per worklist entry, coalesced cooperative dot ----------
__global__ __launch_bounds__(256) void fix_k(const float* __restrict__ x,
                                             const float* __restrict__ w)
{
    int cnt = g_wcnt;
    if (cnt > WLCAP) cnt = WLCAP;
    int l = threadIdx.x & 31;
    int gwarp = (blockIdx.x * 256 + threadIdx.x) >> 5;
    int nwarps = (gridDim.x * 256) >> 5;

    for (int e = gwarp; e < cnt; e += nwarps) {
        unsigned word = g_wl[e];
        int t = (int)(word >> 31);
        int r = (int)(word & 0x7FFFFFFFu);
        int d = r & 63;
        int n = (r >> 6) % NT;
        int bh = r / (NT * HD);
        int b = bh / NH, h = bh - b * NH;
        const float4* xr = (const float4*)(x + (size_t)(b * NT + n) * CH);
        const float4* wr = (const float4*)(w + (size_t)(t * CH + h * HD + d) * CH);
        float s = 0.f;
#pragma unroll
        for (int i = 0; i < 6; i++) {
            float4 a = xr[l + i * 32];
            float4 bb = wr[l + i * 32];
            s = fmaf(a.x, bb.x, s);
            s = fmaf(a.y, bb.y, s);
            s = fmaf(a.z, bb.z, s);
            s = fmaf(a.w, bb.w, s);
        }
#pragma unroll
        for (int o = 16; o; o >>= 1) s += __shfl_xor_sync(0xffffffffu, s, o);
        if (l == 0) (t ? g_k : g_q)[r] = s;
    }
}

// -------- per-(b,h) stats + v int8 quant with fp32 boundary repair ------------
__global__ __launch_bounds__(256) void stats_k(const float* __restrict__ x,
                                               const float* __restrict__ wqkv)
{
    int bh = blockIdx.x;
    size_t base = (size_t)bh * NT * HD;
    const float* q = g_q + base;
    const float* k = g_k + base;
    const float* v = g_v + base;
    int tid = threadIdx.x, w = tid >> 5, l = tid & 31;
    int b = bh / NH, hh = bh - b * NH;

    __shared__ int   vmax[HD];
    __shared__ float svs[HD];
    __shared__ float r1[8], r2[8];
    if (tid < HD) vmax[tid] = 0;
    __syncthreads();

    float sa = 0.f, sb = 0.f;
    for (int i = tid; i < NT * HD; i += 256) {
        sa += fabsf(q[i]);
        sb += fabsf(k[i]);
        atomicMax(&vmax[i & 63], __float_as_int(fabsf(v[i])));
    }
#pragma unroll
    for (int o = 16; o; o >>= 1) {
        sa += __shfl_xor_sync(0xffffffffu, sa, o);
        sb += __shfl_xor_sync(0xffffffffu, sb, o);
    }
    if (l == 0) { r1[w] = sa; r2[w] = sb; }

    for (int n = w; n < NT; n += 8) {
        float q0 = q[n * HD + l],      q1 = q[n * HD + 32 + l];
        float k0 = k[n * HD + l],      k1 = k[n * HD + 32 + l];
        unsigned bq0 = __ballot_sync(0xffffffffu, q0 < 0.f);
        unsigned bq1 = __ballot_sync(0xffffffffu, q1 < 0.f);
        unsigned bk0 = __ballot_sync(0xffffffffu, k0 < 0.f);
        unsigned bk1 = __ballot_sync(0xffffffffu, k1 < 0.f);
        if (l == 0) {
            g_qb[bh * NT + n] = (unsigned long long)bq0 | ((unsigned long long)bq1 << 32);
            g_kb[bh * NT + n] = (unsigned long long)bk0 | ((unsigned long long)bk1 << 32);
        }
    }
    __syncthreads();

    if (tid == 0) {
        float s1 = 0.f, s2 = 0.f;
        for (int i = 0; i < 8; i++) { s1 += r1[i]; s2 += r2[i]; }
        g_sq[bh] = s1 / (float)(NT * HD);
        g_sk[bh] = s2 / (float)(NT * HD);
    }
    if (tid < HD) {
        float mm = __int_as_float(vmax[tid]);
        float s = 127.f / (mm + 1e-6f);
        svs[tid] = s;
        g_vinv[bh * HD + tid] = 1.f / (s + 1e-6f);
    }
    __syncthreads();
    for (int i = tid; i < NT * HD; i += 256) {
        float vv = v[i];
        int d = i & 63;
        float tq = vv * svs[d];
        if (fabsf(tq - rintf(tq)) > 0.498f) {
            int n = i >> 6;
            const float* xr = x + (size_t)(b * NT + n) * CH;
            const float* wr = wqkv + (size_t)(2 * CH + hh * HD + d) * CH;
            vv = dot768(xr, wr);
            tq = vv * svs[d];
        }
        g_v8[base + i] = (signed char)rintf(tq);
    }
}

// -------- relative-position bias gather ---------------------------------------
__global__ __launch_bounds__(256) void bias_k(const float* __restrict__ rpb,
                                              const int* __restrict__ rel)
{
    int i = blockIdx.x * 256 + threadIdx.x;
    if (i < NH * NT * NT) {
        int h = i / (NT * NT);
        int r = i - h * (NT * NT);
        g_bias[i] = rpb[rel[r] * NH + h];
    }
}

// -------- fused attention v2: 4-row batched AV, int4 smem loads ----------------
#define VROW 208
__global__ __launch_bounds__(256) void attn_k()
{
    __shared__ unsigned long long skb[NT];
    __shared__ __align__(16) signed char  svt[HD * VROW];
    __shared__ __align__(16) unsigned char pbuf[32 * VROW];

    int bh = blockIdx.x;
    int half = blockIdx.y;
    int b = bh / NH, h = bh - b * NH;
    size_t base = (size_t)bh * NT * HD;
    int tid = threadIdx.x, w = tid >> 5, l = tid & 31;

    for (int i = tid; i < 32 * VROW / 4; i += 256) ((uint32_t*)pbuf)[i] = 0u;
    for (int i = tid; i < NT * HD; i += 256) {
        int n = i >> 6, d = i & 63;
        svt[d * VROW + n] = g_v8[base + i];
    }
    for (int i = tid; i < NT; i += 256) skb[i] = g_kb[bh * NT + i];
    __syncthreads();

    float p0 = g_sq[bh] * g_sk[bh];
    float fin0 = g_vinv[bh * HD + l]      * (1.0f / 255.0f) * AOSCALE;
    float fin1 = g_vinv[bh * HD + 32 + l] * (1.0f / 255.0f) * AOSCALE;
    const float* brow_base = g_bias + (size_t)h * NT * NT;
    const int4* sv0q = (const int4*)(svt + (size_t)l * VROW);
    const int4* sv1q = (const int4*)(svt + (size_t)(l + 32) * VROW);

    int nbase = 8 * half + w;
    int T = (NT - nbase + 15) / 16;
    int ngroups = T >> 2, tail = T & 3;

    auto softmax_row = [&](int n, int pr) {
        unsigned long long qb = g_qb[bh * NT + n];
        const float* brow = brow_base + (size_t)n * NT;
        float lg[7];
        float mx = -3.0e38f;
#pragma unroll
        for (int j = 0; j < 7; j++) {
            int m = j * 32 + l;
            float val = -3.0e38f;
            if (m < NT) {
                int cnt = 64 - 2 * __popcll(qb ^ skb[m]);
                val = 0.125f * (p0 * (float)cnt) + brow[m];
            }
            lg[j] = val;
            mx = fmaxf(mx, val);
        }
#pragma unroll
        for (int o = 16; o; o >>= 1) mx = fmaxf(mx, __shfl_xor_sync(0xffffffffu, mx, o));
        float sum = 0.f;
#pragma unroll
        for (int j = 0; j < 7; j++) {
            float e = expf(lg[j] - mx);
            lg[j] = e;
            sum += e;
        }
#pragma unroll
        for (int o = 16; o; o >>= 1) sum += __shfl_xor_sync(0xffffffffu, sum, o);
        float rs = 255.f / sum;
        unsigned char* pw = pbuf + pr * VROW;
#pragma unroll
        for (int j = 0; j < 7; j++) {
            int m = j * 32 + l;
            if (m < NT)
                pw[m] = (unsigned char)(int)fminf(rintf(lg[j] * rs), 255.f);
        }
    };

    auto store_row = [&](int n, int ia0, int ia1) {
        float o0 = (float)ia0 * fin0;
        float o1 = (float)ia1 * fin1;
        size_t ob = ((size_t)(b * NT + n)) * CH + h * HD;
        __half h0 = __float2half(o0);
        __half h1 = __float2half(o1);
        g_ah[ob + l]      = h0;
        g_al[ob + l]      = __float2half(o0 - __half2float(h0));
        g_ah[ob + 32 + l] = h1;
        g_al[ob + 32 + l] = __float2half(o1 - __half2float(h1));
    };

    for (int s = 0; s < ngroups; s++) {
        int n0r = nbase + 64 * s;
        __syncwarp();
#pragma unroll
        for (int r = 0; r < 4; r++) softmax_row(n0r + 16 * r, w * 4 + r);
        __syncwarp();

        const int4* pq0 = (const int4*)(pbuf + (w * 4 + 0) * VROW);
        const int4* pq1 = (const int4*)(pbuf + (w * 4 + 1) * VROW);
        const int4* pq2 = (const int4*)(pbuf + (w * 4 + 2) * VROW);
        const int4* pq3 = (const int4*)(pbuf + (w * 4 + 3) * VROW);
        int ia[4][2];
#pragma unroll
        for (int r = 0; r < 4; r++) { ia[r][0] = 0; ia[r][1] = 0; }

#pragma unroll
        for (int gq = 0; gq < VROW / 16; gq++) {
            int4 v0 = sv0q[gq];
            int4 v1 = sv1q[gq];
            int4 pr[4] = {pq0[gq], pq1[gq], pq2[gq], pq3[gq]};
#pragma unroll
            for (int r = 0; r < 4; r++) {
                ia[r][0] = dp4a_us((unsigned)pr[r].x, v0.x, ia[r][0]);
                ia[r][0] = dp4a_us((unsigned)pr[r].y, v0.y, ia[r][0]);
                ia[r][0] = dp4a_us((unsigned)pr[r].z, v0.z, ia[r][0]);
                ia[r][0] = dp4a_us((unsigned)pr[r].w, v0.w, ia[r][0]);
                ia[r][1] = dp4a_us((unsigned)pr[r].x, v1.x, ia[r][1]);
                ia[r][1] = dp4a_us((unsigned)pr[r].y, v1.y, ia[r][1]);
                ia[r][1] = dp4a_us((unsigned)pr[r].z, v1.z, ia[r][1]);
                ia[r][1] = dp4a_us((unsigned)pr[r].w, v1.w, ia[r][1]);
            }
        }
#pragma unroll
        for (int r = 0; r < 4; r++) store_row(n0r + 16 * r, ia[r][0], ia[r][1]);
    }

    if (tail) {
        int n = nbase + 64 * ngroups;
        __syncwarp();
        softmax_row(n, w * 4);
        __syncwarp();
        const int4* pq = (const int4*)(pbuf + (w * 4) * VROW);
        int ia0 = 0, ia1 = 0;
#pragma unroll
        for (int gq = 0; gq < VROW / 16; gq++) {
            int4 v0 = sv0q[gq];
            int4 v1 = sv1q[gq];
            int4 p = pq[gq];
            ia0 = dp4a_us((unsigned)p.x, v0.x, ia0);
            ia0 = dp4a_us((unsigned)p.y, v0.y, ia0);
            ia0 = dp4a_us((unsigned)p.z, v0.z, ia0);
            ia0 = dp4a_us((unsigned)p.w, v0.w, ia0);
            ia1 = dp4a_us((unsigned)p.x, v1.x, ia1);
            ia1 = dp4a_us((unsigned)p.y, v1.y, ia1);
            ia1 = dp4a_us((unsigned)p.z, v1.z, ia1);
            ia1 = dp4a_us((unsigned)p.w, v1.w, ia1);
        }
        store_row(n, ia0, ia1);
    }
}

// ---------------- launch ------------------------------------------------------
extern "C" void kernel_launch(void* const* d_in, const int* in_sizes, int n_in,
                              void* d_out, int out_size)
{
    const float* x     = (const float*)d_in[0];
    const float* wqkv  = (const float*)d_in[1];
    const float* wproj = (const float*)d_in[2];
    const float* bproj = (const float*)d_in[3];
    const float* rpb   = (const float*)d_in[4];
    const int*   rel   = (const int*)d_in[5];
    float* out = (float*)d_out;

    void *p_ah, *p_al, *p_wh, *p_wl, *p_ph, *p_pl;
    cudaGetSymbolAddress(&p_ah, g_ah);
    cudaGetSymbolAddress(&p_al, g_al);
    cudaGetSymbolAddress(&p_wh, g_wh);
    cudaGetSymbolAddress(&p_wl, g_wl16);
    cudaGetSymbolAddress(&p_ph, g_ph);
    cudaGetSymbolAddress(&p_pl, g_pl);

    cudaFuncSetAttribute(gemm_mma<0>, cudaFuncAttributeMaxDynamicSharedMemorySize, DSMEM);
    cudaFuncSetAttribute(gemm_mma<1>, cudaFuncAttributeMaxDynamicSharedMemorySize, DSMEM);

    reset_k<<<1, 1>>>();

    int n8x = ROWS * CH / 8;
    int n8w = QKN * CH / 8;
    int n8p = CH * CH / 8;
    split8_k<<<(n8x + 255) / 256, 256>>>(x, (__half*)p_ah, (__half*)p_al, 1.0f, n8x);
    split8_k<<<(n8w + 255) / 256, 256>>>(wqkv, (__half*)p_wh, (__half*)p_wl, WSCALE, n8w);
    split8_k<<<(n8p + 255) / 256, 256>>>(wproj, (__half*)p_ph, (__half*)p_pl, WSCALE, n8p);

    gemm_mma<0><<<dim3(QKN / 128, (ROWS + 255) / 256), 512, DSMEM>>>(
        (const __half*)p_ah, (const __half*)p_al,
        (const __half*)p_wh, (const __half*)p_wl,
        nullptr, nullptr, ROWS, QKN);

    const int PER = BHN * NT * HD;
    scan_k<<<(2 * PER / 4 + 255) / 256, 256>>>();
    fix_k<<<512, 256>>>(x, wqkv);

    stats_k<<<BHN, 256>>>(x, wqkv);
    bias_k<<<(NH * NT * NT + 255) / 256, 256>>>(rpb, rel);

    attn_k<<<dim3(BHN, 2), 256>>>();

    gemm_mma<1><<<dim3(CH / 128, (ROWS + 255) / 256), 512, DSMEM>>>(
        (const __half*)p_ah, (const __half*)p_al,
        (const __half*)p_ph, (const __half*)p_pl,
        bproj, out, ROWS, CH);
}

// round 16
// speedup vs baseline: 1.4529x; 1.0578x over previous
#include <cuda_runtime.h>
#include <cuda_fp16.h>
#include <math.h>
#include <stdint.h>

#define BATCH 64
#define NT    197
#define CH    768
#define NH    12
#define HD    64
#define BHN   (BATCH*NH)      // 768
#define ROWS  (BATCH*NT)      // 12608
#define QKN   (3*CH)          // 2304
#define KDIM  768
#define KC    64              // K per chunk
#define NCHUNK (KDIM/KC)      // 12

// 256x128 CTA tile, 512 threads, 16 warps (4x4 warp grid, warp tile 64x32)
#define TILEA  (256*KC*2)     // 32768 bytes (A: 256 rows x 128B)
#define TILEBB (128*KC*2)     // 16384 bytes (B: 128 rows x 128B)
#define STAGEB (2*TILEA + 2*TILEBB)   // 98304 per stage
#define DSMEM  (2*STAGEB + 128)       // ~192KB

#define WSCALE   64.0f
#define AOSCALE  64.0f
#define INV_QKV  (1.0f/64.0f)
#define INV_PROJ (1.0f/4096.0f)
#define QK_TAU   1.5e-3f
#define WLCAP    (1 << 20)    // worklist capacity (expected ~46K entries)

// ---------------- scratch ------------------------------------------------------
__device__ float               g_q[(size_t)BHN*NT*HD];
__device__ float               g_k[(size_t)BHN*NT*HD];
__device__ float               g_v[(size_t)BHN*NT*HD];
__device__ unsigned long long  g_qb[BHN*NT];
__device__ unsigned long long  g_kb[BHN*NT];
__device__ float               g_sq[BHN];
__device__ float               g_sk[BHN];
__device__ float               g_vinv[BHN*HD];
__device__ signed char         g_v8[(size_t)BHN*NT*HD];
__device__ float               g_bias[NH*NT*NT];
__device__ unsigned int        g_wl[WLCAP];
__device__ int                 g_wcnt;
__device__ __align__(16) __half g_ah[(size_t)ROWS*CH];
__device__ __align__(16) __half g_al[(size_t)ROWS*CH];
__device__ __align__(16) __half g_wh[(size_t)QKN*CH];
__device__ __align__(16) __half g_wl16[(size_t)QKN*CH];
__device__ __align__(16) __half g_ph[(size_t)CH*CH];
__device__ __align__(16) __half g_pl[(size_t)CH*CH];

// ---------------- PTX helpers -------------------------------------------------
__device__ __forceinline__ uint32_t s2u(const void* p) {
    uint32_t r;
    asm("{ .reg .u64 t; cvta.to.shared.u64 t, %1; cvt.u32.u64 %0, t; }" : "=r"(r) : "l"(p));
    return r;
}
__device__ __forceinline__ void cp16(uint32_t saddr, const void* gaddr, uint32_t srcsize) {
    asm volatile("cp.async.cg.shared.global [%0], [%1], 16, %2;"
                 :: "r"(saddr), "l"(gaddr), "r"(srcsize) : "memory");
}
__device__ __forceinline__ void cp_commit() {
    asm volatile("cp.async.commit_group;" ::: "memory");
}
template<int N> __device__ __forceinline__ void cp_wait() {
    asm volatile("cp.async.wait_group %0;" :: "n"(N) : "memory");
}
__device__ __forceinline__ void ldsm4(uint32_t a, uint32_t& r0, uint32_t& r1,
                                      uint32_t& r2, uint32_t& r3) {
    asm volatile("ldmatrix.sync.aligned.m8n8.x4.shared.b16 {%0,%1,%2,%3}, [%4];"
                 : "=r"(r0), "=r"(r1), "=r"(r2), "=r"(r3) : "r"(a));
}
__device__ __forceinline__ void mma16816(float* c, const uint32_t* a,
                                         uint32_t b0, uint32_t b1) {
    asm volatile("mma.sync.aligned.m16n8k16.row.col.f32.f16.f16.f32 "
                 "{%0,%1,%2,%3}, {%4,%5,%6,%7}, {%8,%9}, {%0,%1,%2,%3};"
                 : "+f"(c[0]), "+f"(c[1]), "+f"(c[2]), "+f"(c[3])
                 : "r"(a[0]), "r"(a[1]), "r"(a[2]), "r"(a[3]), "r"(b0), "r"(b1));
}
__device__ __forceinline__ int dp4a_us(unsigned int a, int b, int c) {
    int d;
    asm("dp4a.u32.s32 %0, %1, %2, %3;" : "=r"(d) : "r"(a), "r"(b), "r"(c));
    return d;
}

__device__ __forceinline__ float dot768(const float* __restrict__ xr,
                                        const float* __restrict__ wr)
{
    const float4* a4 = (const float4*)xr;
    const float4* b4 = (const float4*)wr;
    float s0 = 0.f, s1 = 0.f, s2 = 0.f, s3 = 0.f;
#pragma unroll 4
    for (int i = 0; i < CH / 4; i++) {
        float4 a = a4[i], b = b4[i];
        s0 = fmaf(a.x, b.x, s0);
        s1 = fmaf(a.y, b.y, s1);
        s2 = fmaf(a.z, b.z, s2);
        s3 = fmaf(a.w, b.w, s3);
    }
    return (s0 + s1) + (s2 + s3);
}

// ---------------- fp16 hi/lo split ---------------------------------------------
__device__ __forceinline__ void splith2(float x, float y, float s, uint32_t& h, uint32_t& l) {
    float xs = x * s, ys = y * s;
    __half hx = __float2half(xs), hy = __float2half(ys);
    __half lx = __float2half(xs - __half2float(hx));
    __half ly = __float2half(ys - __half2float(hy));
    h = (uint32_t)__half_as_ushort(hx) | ((uint32_t)__half_as_ushort(hy) << 16);
    l = (uint32_t)__half_as_ushort(lx) | ((uint32_t)__half_as_ushort(ly) << 16);
}
__global__ __launch_bounds__(256) void split8_k(const float* __restrict__ in,
                                                __half* __restrict__ hi,
                                                __half* __restrict__ lo,
                                                float s, int n8)
{
    int i = blockIdx.x * 256 + threadIdx.x;
    if (i >= n8) return;
    float4 a = ((const float4*)in)[i * 2];
    float4 b = ((const float4*)in)[i * 2 + 1];
    uint4 H, L;
    splith2(a.x, a.y, s, H.x, L.x);
    splith2(a.z, a.w, s, H.y, L.y);
    splith2(b.x, b.y, s, H.z, L.z);
    splith2(b.z, b.w, s, H.w, L.w);
    ((uint4*)hi)[i] = H;
    ((uint4*)lo)[i] = L;
}

__global__ void reset_k() { g_wcnt = 0; }

// ---------------- mma.sync fp16x3 GEMM -----------------------------------------
// MODE 0 epilogue: q/k values under QK_TAU are APPENDED to the repair worklist
// (append only — the fp32 recompute stays in the warp-cooperative fix_k).
template<int MODE>
__global__ __launch_bounds__(512)
void gemm_mma(const __half* __restrict__ Ah, const __half* __restrict__ Al,
              const __half* __restrict__ Bh, const __half* __restrict__ Bl,
              const float* __restrict__ bias, float* __restrict__ Cout, int M, int Nn)
{
    extern __shared__ char dyn[];
    uint32_t dbase = s2u(dyn);
    uint32_t pad = (128u - (dbase & 127u)) & 127u;
    uint32_t S = dbase + pad;

    int t = threadIdx.x;
    int wid = t >> 5, l = t & 31;
    int m0 = blockIdx.y * 256;
    int n0 = blockIdx.x * 128;

    int lar = t >> 3, lac = t & 7;
    int lbr = t >> 2, lbc = (t & 3) << 1;

    int r8 = l & 7, mi = l >> 3;
    int rsel = ((mi & 1) << 3) + r8;
    int hm = mi >> 1;
    int wm = (wid >> 2) * 64;
    int wn = (wid & 3) * 32;

    uint32_t apart[4]; int ax[4];
#pragma unroll
    for (int i = 0; i < 4; i++) {
        int row = wm + i * 16 + rsel;
        apart[i] = (uint32_t)(row * 128);
        ax[i] = row & 7;
    }
    uint32_t bpart[2]; int bx[2];
#pragma unroll
    for (int jj = 0; jj < 2; jj++) {
        int row = wn + jj * 16 + rsel;
        bpart[jj] = (uint32_t)(row * 128);
        bx[jj] = row & 7;
    }

    float acc[4][4][4];
#pragma unroll
    for (int i = 0; i < 4; i++)
#pragma unroll
        for (int j = 0; j < 4; j++)
#pragma unroll
            for (int e = 0; e < 4; e++) acc[i][j][e] = 0.f;

    const __half* Asrc[2] = {Ah, Al};
    const __half* Bsrc[2] = {Bh, Bl};

    auto load_stage = [&](int c) {
        uint32_t st = S + (uint32_t)(c & 1) * STAGEB;
        int k0 = c * KC;
#pragma unroll
        for (int ti = 0; ti < 2; ti++) {
#pragma unroll
            for (int i = 0; i < 4; i++) {
                int rr = lar + i * 64;
                int grow = m0 + rr;
                uint32_t ss = st + (uint32_t)ti * TILEA + (uint32_t)(rr * 128)
                              + (uint32_t)((lac ^ (rr & 7)) << 4);
                const void* g = (const char*)Asrc[ti]
                              + (((size_t)grow * KDIM + k0 + lac * 8) * 2);
                cp16(ss, g, (grow < M) ? 16u : 0u);
            }
        }
#pragma unroll
        for (int ti = 0; ti < 2; ti++) {
#pragma unroll
            for (int i = 0; i < 2; i++) {
                int cc = lbc + i;
                uint32_t ss = st + 2u * TILEA + (uint32_t)ti * TILEBB
                              + (uint32_t)(lbr * 128)
                              + (uint32_t)((cc ^ (lbr & 7)) << 4);
                const void* g = (const char*)Bsrc[ti]
                              + (((size_t)(n0 + lbr) * KDIM + k0 + cc * 8) * 2);
                cp16(ss, g, 16u);
            }
        }
        cp_commit();
    };

    load_stage(0);

    for (int c = 0; c < NCHUNK; c++) {
        if (c + 1 < NCHUNK) { load_stage(c + 1); cp_wait<1>(); }
        else                { cp_wait<0>(); }
        __syncthreads();

        uint32_t st = S + (uint32_t)(c & 1) * STAGEB;
        uint32_t tAh = st;
        uint32_t tAl = st + TILEA;
        uint32_t tBh = st + 2 * TILEA;
        uint32_t tBl = st + 2 * TILEA + TILEBB;

#pragma unroll
        for (int ks = 0; ks < 4; ks++) {
            int cbase = ks * 2 + hm;
            uint32_t ah[4][4], al[4][4], bh[2][4], bl[2][4];
#pragma unroll
            for (int i = 0; i < 4; i++)
                ldsm4(tAh + apart[i] + (uint32_t)((cbase ^ ax[i]) << 4),
                      ah[i][0], ah[i][1], ah[i][2], ah[i][3]);
#pragma unroll
            for (int jj = 0; jj < 2; jj++)
                ldsm4(tBh + bpart[jj] + (uint32_t)((cbase ^ bx[jj]) << 4),
                      bh[jj][0], bh[jj][1], bh[jj][2], bh[jj][3]);
#pragma unroll
            for (int jj = 0; jj < 2; jj++)
                ldsm4(tBl + bpart[jj] + (uint32_t)((cbase ^ bx[jj]) << 4),
                      bl[jj][0], bl[jj][1], bl[jj][2], bl[jj][3]);
#pragma unroll
            for (int i = 0; i < 4; i++)
                ldsm4(tAl + apart[i] + (uint32_t)((cbase ^ ax[i]) << 4),
                      al[i][0], al[i][1], al[i][2], al[i][3]);

#pragma unroll
            for (int i = 0; i < 4; i++) {
                mma16816(acc[i][0], ah[i], bh[0][0], bh[0][2]);
                mma16816(acc[i][1], ah[i], bh[0][1], bh[0][3]);
                mma16816(acc[i][2], ah[i], bh[1][0], bh[1][2]);
                mma16816(acc[i][3], ah[i], bh[1][1], bh[1][3]);
            }
#pragma unroll
            for (int i = 0; i < 4; i++) {
                mma16816(acc[i][0], ah[i], bl[0][0], bl[0][2]);
                mma16816(acc[i][1], ah[i], bl[0][1], bl[0][3]);
                mma16816(acc[i][2], ah[i], bl[1][0], bl[1][2]);
                mma16816(acc[i][3], ah[i], bl[1][1], bl[1][3]);
            }
#pragma unroll
            for (int i = 0; i < 4; i++) {
                mma16816(acc[i][0], al[i], bh[0][0], bh[0][2]);
                mma16816(acc[i][1], al[i], bh[0][1], bh[0][3]);
                mma16816(acc[i][2], al[i], bh[1][0], bh[1][2]);
                mma16816(acc[i][3], al[i], bh[1][1], bh[1][3]);
            }
        }
        __syncthreads();
    }

    int gID = l >> 2, tig = l & 3;
    if (MODE == 0) {
        int which = n0 / CH;
        float* P = (which == 0) ? g_q : (which == 1) ? g_k : g_v;
        int rem0 = n0 - which * CH;
        bool is_qk = (which < 2);
#pragma unroll
        for (int i = 0; i < 4; i++) {
#pragma unroll
            for (int half = 0; half < 2; half++) {
                int m = m0 + wm + i * 16 + gID + half * 8;
                if (m >= M) continue;
                int b = m / NT, n = m - b * NT;
#pragma unroll
                for (int j = 0; j < 4; j++) {
                    int rem = rem0 + wn + j * 8 + tig * 2;
                    int h = rem >> 6, d = rem & 63;
                    float2 v2 = half
                        ? make_float2(acc[i][j][2] * INV_QKV, acc[i][j][3] * INV_QKV)
                        : make_float2(acc[i][j][0] * INV_QKV, acc[i][j][1] * INV_QKV);
                    size_t r = (((size_t)(b * NH + h)) * NT + n) * HD + d;
                    *(float2*)&P[r] = v2;
                    if (is_qk) {
                        // append-only: repair math stays in fix_k
                        if (fabsf(v2.x) < QK_TAU) {
                            int pos = atomicAdd(&g_wcnt, 1);
                            if (pos < WLCAP)
                                g_wl[pos] = (unsigned)r | ((unsigned)which << 31);
                        }
                        if (fabsf(v2.y) < QK_TAU) {
                            int pos = atomicAdd(&g_wcnt, 1);
                            if (pos < WLCAP)
                                g_wl[pos] = (unsigned)(r + 1) | ((unsigned)which << 31);
                        }
                    }
                }
            }
        }
    } else {
#pragma unroll
        for (int i = 0; i < 4; i++) {
#pragma unroll
            for (int half = 0; half < 2; half++) {
                int m = m0 + wm + i * 16 + gID + half * 8;
                if (m >= M) continue;
                float* crow = Cout + (size_t)m * CH;
#pragma unroll
                for (int j = 0; j < 4; j++) {
                    int cg = n0 + wn + j * 8 + tig * 2;
                    float2 bb2 = *(const float2*)&bias[cg];
                    float2 v2 = half
                        ? make_float2(acc[i][j][2] * INV_PROJ + bb2.x, acc[i][j][3] * INV_PROJ + bb2.y)
                        : make_float2(acc[i][j][0] * INV_PROJ + bb2.x, acc[i][j][1] * INV_PROJ + bb2.y);
                    *(float2*)&crow[cg] = v2;
                }
            }
        }
    }
}

// -------- fix: one warp per worklist entry, coalesced cooperative dot ----------
__global__ __launch_bounds__(256) void fix_k(const float* __restrict__ x,
                                             const float* __restrict__ w)
{
    int cnt = g_wcnt;
    if (cnt > WLCAP) cnt = WLCAP;
    int l = threadIdx.x & 31;
    int gwarp = (blockIdx.x * 256 + threadIdx.x) >> 5;
    int nwarps = (gridDim.x * 256) >> 5;

    for (int e = gwarp; e < cnt; e += nwarps) {
        unsigned word = g_wl[e];
        int t = (int)(word >> 31);
        int r = (int)(word & 0x7FFFFFFFu);
        int d = r & 63;
        int n = (r >> 6) % NT;
        int bh = r / (NT * HD);
        int b = bh / NH, h = bh - b * NH;
        const float4* xr = (const float4*)(x + (size_t)(b * NT + n) * CH);
        const float4* wr = (const float4*)(w + (size_t)(t * CH + h * HD + d) * CH);
        float s = 0.f;
#pragma unroll
        for (int i = 0; i < 6; i++) {
            float4 a = xr[l + i * 32];
            float4 bb = wr[l + i * 32];
            s = fmaf(a.x, bb.x, s);
            s = fmaf(a.y, bb.y, s);
            s = fmaf(a.z, bb.z, s);
            s = fmaf(a.w, bb.w, s);
        }
#pragma unroll
        for (int o = 16; o; o >>= 1) s += __shfl_xor_sync(0xffffffffu, s, o);
        if (l == 0) (t ? g_k : g_q)[r] = s;
    }
}

// -------- per-(b,h) stats + v int8 quant with fp32 boundary repair ------------
__global__ __launch_bounds__(256) void stats_k(const float* __restrict__ x,
                                               const float* __restrict__ wqkv)
{
    int bh = blockIdx.x;
    size_t base = (size_t)bh * NT * HD;
    const float* q = g_q + base;
    const float* k = g_k + base;
    const float* v = g_v + base;
    int tid = threadIdx.x, w = tid >> 5, l = tid & 31;
    int b = bh / NH, hh = bh - b * NH;

    __shared__ int   vmax[HD];
    __shared__ float svs[HD];
    __shared__ float r1[8], r2[8];
    if (tid < HD) vmax[tid] = 0;
    __syncthreads();

    float sa = 0.f, sb = 0.f;
    for (int i = tid; i < NT * HD; i += 256) {
        sa += fabsf(q[i]);
        sb += fabsf(k[i]);
        atomicMax(&vmax[i & 63], __float_as_int(fabsf(v[i])));
    }
#pragma unroll
    for (int o = 16; o; o >>= 1) {
        sa += __shfl_xor_sync(0xffffffffu, sa, o);
        sb += __shfl_xor_sync(0xffffffffu, sb, o);
    }
    if (l == 0) { r1[w] = sa; r2[w] = sb; }

    for (int n = w; n < NT; n += 8) {
        float q0 = q[n * HD + l],      q1 = q[n * HD + 32 + l];
        float k0 = k[n * HD + l],      k1 = k[n * HD + 32 + l];
        unsigned bq0 = __ballot_sync(0xffffffffu, q0 < 0.f);
        unsigned bq1 = __ballot_sync(0xffffffffu, q1 < 0.f);
        unsigned bk0 = __ballot_sync(0xffffffffu, k0 < 0.f);
        unsigned bk1 = __ballot_sync(0xffffffffu, k1 < 0.f);
        if (l == 0) {
            g_qb[bh * NT + n] = (unsigned long long)bq0 | ((unsigned long long)bq1 << 32);
            g_kb[bh * NT + n] = (unsigned long long)bk0 | ((unsigned long long)bk1 << 32);
        }
    }
    __syncthreads();

    if (tid == 0) {
        float s1 = 0.f, s2 = 0.f;
        for (int i = 0; i < 8; i++) { s1 += r1[i]; s2 += r2[i]; }
        g_sq[bh] = s1 / (float)(NT * HD);
        g_sk[bh] = s2 / (float)(NT * HD);
    }
    if (tid < HD) {
        float mm = __int_as_float(vmax[tid]);
        float s = 127.f / (mm + 1e-6f);
        svs[tid] = s;
        g_vinv[bh * HD + tid] = 1.f / (s + 1e-6f);
    }
    __syncthreads();
    // v8 quant: float4 loads + char4 stores (per-element ops identical)
    const float4* v4p = (const float4*)v;
    for (int i4 = tid; i4 < NT * HD / 4; i4 += 256) {
        float4 vv4 = v4p[i4];
        int i0 = i4 * 4;
        int d0 = i0 & 63;
        int n = i0 >> 6;
        float va[4] = {vv4.x, vv4.y, vv4.z, vv4.w};
        signed char o4[4];
#pragma unroll
        for (int j = 0; j < 4; j++) {
            int d = d0 + j;
            float tq = va[j] * svs[d];
            if (fabsf(tq - rintf(tq)) > 0.498f) {
                const float* xr = x + (size_t)(b * NT + n) * CH;
                const float* wr = wqkv + (size_t)(2 * CH + hh * HD + d) * CH;
                float vv = dot768(xr, wr);
                tq = vv * svs[d];
            }
            o4[j] = (signed char)rintf(tq);
        }
        *(uchar4*)&g_v8[base + i0] = *(uchar4*)o4;
    }
}

// -------- relative-position bias gather ---------------------------------------
__global__ __launch_bounds__(256) void bias_k(const float* __restrict__ rpb,
                                              const int* __restrict__ rel)
{
    int i = blockIdx.x * 256 + threadIdx.x;
    if (i < NH * NT * NT) {
        int h = i / (NT * NT);
        int r = i - h * (NT * NT);
        g_bias[i] = rpb[rel[r] * NH + h];
    }
}

// -------- fused attention v2: 4-row batched AV, int4 smem loads ----------------
#define VROW 208
__global__ __launch_bounds__(256) void attn_k()
{
    __shared__ unsigned long long skb[NT];
    __shared__ __align__(16) signed char  svt[HD * VROW];
    __shared__ __align__(16) unsigned char pbuf[32 * VROW];

    int bh = blockIdx.x;
    int half = blockIdx.y;
    int b = bh / NH, h = bh - b * NH;
    size_t base = (size_t)bh * NT * HD;
    int tid = threadIdx.x, w = tid >> 5, l = tid & 31;

    for (int i = tid; i < 32 * VROW / 4; i += 256) ((uint32_t*)pbuf)[i] = 0u;
    for (int i = tid; i < NT * HD; i += 256) {
        int n = i >> 6, d = i & 63;
        svt[d * VROW + n] = g_v8[base + i];
    }
    for (int i = tid; i < NT; i += 256) skb[i] = g_kb[bh * NT + i];
    __syncthreads();

    float p0 = g_sq[bh] * g_sk[bh];
    float fin0 = g_vinv[bh * HD + l]      * (1.0f / 255.0f) * AOSCALE;
    float fin1 = g_vinv[bh * HD + 32 + l] * (1.0f / 255.0f) * AOSCALE;
    const float* brow_base = g_bias + (size_t)h * NT * NT;
    const int4* sv0q = (const int4*)(svt + (size_t)l * VROW);
    const int4* sv1q = (const int4*)(svt + (size_t)(l + 32) * VROW);

    int nbase = 8 * half + w;
    int T = (NT - nbase + 15) / 16;
    int ngroups = T >> 2, tail = T & 3;

    auto softmax_row = [&](int n, int pr) {
        unsigned long long qb = g_qb[bh * NT + n];
        const float* brow = brow_base + (size_t)n * NT;
        float lg[7];
        float mx = -3.0e38f;
#pragma unroll
        for (int j = 0; j < 7; j++) {
            int m = j * 32 + l;
            float val = -3.0e38f;
            if (m < NT) {
                int cnt = 64 - 2 * __popcll(qb ^ skb[m]);
                val = 0.125f * (p0 * (float)cnt) + brow[m];
            }
            lg[j] = val;
            mx = fmaxf(mx, val);
        }
#pragma unroll
        for (int o = 16; o; o >>= 1) mx = fmaxf(mx, __shfl_xor_sync(0xffffffffu, mx, o));
        float sum = 0.f;
#pragma unroll
        for (int j = 0; j < 7; j++) {
            float e = expf(lg[j] - mx);
            lg[j] = e;
            sum += e;
        }
#pragma unroll
        for (int o = 16; o; o >>= 1) sum += __shfl_xor_sync(0xffffffffu, sum, o);
        float rs = 255.f / sum;
        unsigned char* pw = pbuf + pr * VROW;
#pragma unroll
        for (int j = 0; j < 7; j++) {
            int m = j * 32 + l;
            if (m < NT)
                pw[m] = (unsigned char)(int)fminf(rintf(lg[j] * rs), 255.f);
        }
    };

    auto store_row = [&](int n, int ia0, int ia1) {
        float o0 = (float)ia0 * fin0;
        float o1 = (float)ia1 * fin1;
        size_t ob = ((size_t)(b * NT + n)) * CH + h * HD;
        __half h0 = __float2half(o0);
        __half h1 = __float2half(o1);
        g_ah[ob + l]      = h0;
        g_al[ob + l]      = __float2half(o0 - __half2float(h0));
        g_ah[ob + 32 + l] = h1;
        g_al[ob + 32 + l] = __float2half(o1 - __half2float(h1));
    };

    for (int s = 0; s < ngroups; s++) {
        int n0r = nbase + 64 * s;
        __syncwarp();
#pragma unroll
        for (int r = 0; r < 4; r++) softmax_row(n0r + 16 * r, w * 4 + r);
        __syncwarp();

        const int4* pq0 = (const int4*)(pbuf + (w * 4 + 0) * VROW);
        const int4* pq1 = (const int4*)(pbuf + (w * 4 + 1) * VROW);
        const int4* pq2 = (const int4*)(pbuf + (w * 4 + 2) * VROW);
        const int4* pq3 = (const int4*)(pbuf + (w * 4 + 3) * VROW);
        int ia[4][2];
#pragma unroll
        for (int r = 0; r < 4; r++) { ia[r][0] = 0; ia[r][1] = 0; }

#pragma unroll
        for (int gq = 0; gq < VROW / 16; gq++) {
            int4 v0 = sv0q[gq];
            int4 v1 = sv1q[gq];
            int4 pr[4] = {pq0[gq], pq1[gq], pq2[gq], pq3[gq]};
#pragma unroll
            for (int r = 0; r < 4; r++) {
                ia[r][0] = dp4a_us((unsigned)pr[r].x, v0.x, ia[r][0]);
                ia[r][0] = dp4a_us((unsigned)pr[r].y, v0.y, ia[r][0]);
                ia[r][0] = dp4a_us((unsigned)pr[r].z, v0.z, ia[r][0]);
                ia[r][0] = dp4a_us((unsigned)pr[r].w, v0.w, ia[r][0]);
                ia[r][1] = dp4a_us((unsigned)pr[r].x, v1.x, ia[r][1]);
                ia[r][1] = dp4a_us((unsigned)pr[r].y, v1.y, ia[r][1]);
                ia[r][1] = dp4a_us((unsigned)pr[r].z, v1.z, ia[r][1]);
                ia[r][1] = dp4a_us((unsigned)pr[r].w, v1.w, ia[r][1]);
            }
        }
#pragma unroll
        for (int r = 0; r < 4; r++) store_row(n0r + 16 * r, ia[r][0], ia[r][1]);
    }

    if (tail) {
        int n = nbase + 64 * ngroups;
        __syncwarp();
        softmax_row(n, w * 4);
        __syncwarp();
        const int4* pq = (const int4*)(pbuf + (w * 4) * VROW);
        int ia0 = 0, ia1 = 0;
#pragma unroll
        for (int gq = 0; gq < VROW / 16; gq++) {
            int4 v0 = sv0q[gq];
            int4 v1 = sv1q[gq];
            int4 p = pq[gq];
            ia0 = dp4a_us((unsigned)p.x, v0.x, ia0);
            ia0 = dp4a_us((unsigned)p.y, v0.y, ia0);
            ia0 = dp4a_us((unsigned)p.z, v0.z, ia0);
            ia0 = dp4a_us((unsigned)p.w, v0.w, ia0);
            ia1 = dp4a_us((unsigned)p.x, v1.x, ia1);
            ia1 = dp4a_us((unsigned)p.y, v1.y, ia1);
            ia1 = dp4a_us((unsigned)p.z, v1.z, ia1);
            ia1 = dp4a_us((unsigned)p.w, v1.w, ia1);
        }
        store_row(n, ia0, ia1);
    }
}

// ---------------- launch ------------------------------------------------------
extern "C" void kernel_launch(void* const* d_in, const int* in_sizes, int n_in,
                              void* d_out, int out_size)
{
    const float* x     = (const float*)d_in[0];
    const float* wqkv  = (const float*)d_in[1];
    const float* wproj = (const float*)d_in[2];
    const float* bproj = (const float*)d_in[3];
    const float* rpb   = (const float*)d_in[4];
    const int*   rel   = (const int*)d_in[5];
    float* out = (float*)d_out;

    void *p_ah, *p_al, *p_wh, *p_wl, *p_ph, *p_pl;
    cudaGetSymbolAddress(&p_ah, g_ah);
    cudaGetSymbolAddress(&p_al, g_al);
    cudaGetSymbolAddress(&p_wh, g_wh);
    cudaGetSymbolAddress(&p_wl, g_wl16);
    cudaGetSymbolAddress(&p_ph, g_ph);
    cudaGetSymbolAddress(&p_pl, g_pl);

    cudaFuncSetAttribute(gemm_mma<0>, cudaFuncAttributeMaxDynamicSharedMemorySize, DSMEM);
    cudaFuncSetAttribute(gemm_mma<1>, cudaFuncAttributeMaxDynamicSharedMemorySize, DSMEM);

    reset_k<<<1, 1>>>();

    int n8x = ROWS * CH / 8;
    int n8w = QKN * CH / 8;
    int n8p = CH * CH / 8;
    split8_k<<<(n8x + 255) / 256, 256>>>(x, (__half*)p_ah, (__half*)p_al, 1.0f, n8x);
    split8_k<<<(n8w + 255) / 256, 256>>>(wqkv, (__half*)p_wh, (__half*)p_wl, WSCALE, n8w);
    split8_k<<<(n8p + 255) / 256, 256>>>(wproj, (__half*)p_ph, (__half*)p_pl, WSCALE, n8p);

    gemm_mma<0><<<dim3(QKN / 128, (ROWS + 255) / 256), 512, DSMEM>>>(
        (const __half*)p_ah, (const __half*)p_al,
        (const __half*)p_wh, (const __half*)p_wl,
        nullptr, nullptr, ROWS, QKN);

    fix_k<<<512, 256>>>(x, wqkv);

    stats_k<<<BHN, 256>>>(x, wqkv);
    bias_k<<<(NH * NT * NT + 255) / 256, 256>>>(rpb, rel);

    attn_k<<<dim3(BHN, 2), 256>>>();

    gemm_mma<1><<<dim3(CH / 128, (ROWS + 255) / 256), 512, DSMEM>>>(
        (const __half*)p_ah, (const __half*)p_al,
        (const __half*)p_ph, (const __half*)p_pl,
        bproj, out, ROWS, CH);
}